// round 7
// baseline (speedup 1.0000x reference)
#include <cuda_runtime.h>
#include <cuda_bf16.h>
#include <cstdint>

// Problem constants (fixed shapes from reference)
#define NB    32
#define NA    1024
#define PPB   65536      // pairs per batch = NA * NEIGH
#define NTYPE 4
#define NWAVE 16
#define NPAIR (NB * PPB)                 // 2,097,152
#define NOUT  (NB * NA * NTYPE * NWAVE)  // 2,097,152 floats

// ---------------------------------------------------------------------------
// Kernel 1: zero the accumulator (d_out is poisoned to 0xAA by the harness)
// ---------------------------------------------------------------------------
__global__ void zero_kernel(float4* __restrict__ out) {
    int i = blockIdx.x * blockDim.x + threadIdx.x;   // NOUT/4 threads
    out[i] = make_float4(0.f, 0.f, 0.f, 0.f);
}

// ---------------------------------------------------------------------------
// Kernel 2: per-pair radial basis + scatter-add into dens (= d_out)
// ---------------------------------------------------------------------------
__global__ void __launch_bounds__(256)
pair_kernel(const float* __restrict__ coords,      // (NB*NA, 3)
            const float* __restrict__ shifts,      // (NB*PPB, 3)
            const float* __restrict__ rs,          // (NTYPE, NWAVE)
            const float* __restrict__ inta,        // (NTYPE, NWAVE)
            const int*   __restrict__ atom_index,  // (NB, 2, PPB)
            const int*   __restrict__ species,     // (NB*NA)
            float*       __restrict__ dens)        // (NB*NA, NTYPE*NWAVE)
{
    __shared__ float s_rs[NTYPE * NWAVE];
    __shared__ float s_ia[NTYPE * NWAVE];
    int t = threadIdx.x;
    if (t < NTYPE * NWAVE) {
        s_rs[t] = rs[t];
        s_ia[t] = inta[t];
    }
    __syncthreads();

    unsigned p = blockIdx.x * blockDim.x + t;        // exactly NPAIR threads
    unsigned b = p >> 16;                            // batch (PPB = 2^16)
    unsigned j = p & (PPB - 1);

    const int* ai = atom_index + (size_t)b * 2u * PPB;
    int i0 = __ldg(ai + j);
    int i1 = __ldg(ai + PPB + j);
    unsigned g0 = (b << 10) + (unsigned)i0;          // NA = 2^10
    unsigned g1 = (b << 10) + (unsigned)i1;

    // shift (coalesced 12B/thread)
    const float* shp = shifts + 3ull * p;
    float sx = shp[0], sy = shp[1], sz = shp[2];

    // validity mask (padding check — always true for these inputs, but cheap)
    bool valid = (sx > -1e9f) && (sy > -1e9f) && (sz > -1e9f);

    // center / neighbor coords: random within a 12KB per-batch window -> L1 hits
    const float* c0 = coords + 3ull * g0;
    const float* c1 = coords + 3ull * g1;
    float dx = __ldg(c0 + 0) - __ldg(c1 + 0) + sx;
    float dy = __ldg(c0 + 1) - __ldg(c1 + 1) + sy;
    float dz = __ldg(c0 + 2) - __ldg(c1 + 2) + sz;
    float r = sqrtf(dx * dx + dy * dy + dz * dz);

    // fc = 0.5*(cos(pi*min(r/5,1))+1); zero contribution if r >= 5 or invalid
    if (!valid || r >= 5.0f) return;
    float fc = 0.5f * (__cosf(r * 0.628318530717958647692f) + 1.0f);

    int s = __ldg(species + g0);
    const float* prs = s_rs + s * NWAVE;
    const float* pia = s_ia + s * NWAVE;

    float v[NWAVE];
#pragma unroll
    for (int w = 0; w < NWAVE; ++w) {
        float d = r - prs[w];
        v[w] = fc * __expf(-10.0f * pia[w] * d * d);
    }

    // 64B-aligned destination row: g0*64 floats + s*16 floats
    float* dst = dens + ((size_t)g0 * (NTYPE * NWAVE) + s * NWAVE);
#if defined(USE_SCALAR_ATOMICS)
#pragma unroll
    for (int w = 0; w < NWAVE; ++w) atomicAdd(dst + w, v[w]);
#else
    float4* dst4 = (float4*)dst;   // 16B-aligned: row base is 64B aligned
    atomicAdd(dst4 + 0, make_float4(v[ 0], v[ 1], v[ 2], v[ 3]));
    atomicAdd(dst4 + 1, make_float4(v[ 4], v[ 5], v[ 6], v[ 7]));
    atomicAdd(dst4 + 2, make_float4(v[ 8], v[ 9], v[10], v[11]));
    atomicAdd(dst4 + 3, make_float4(v[12], v[13], v[14], v[15]));
#endif
}

// ---------------------------------------------------------------------------
// Kernel 3: square in place
// ---------------------------------------------------------------------------
__global__ void square_kernel(float4* __restrict__ out) {
    int i = blockIdx.x * blockDim.x + threadIdx.x;   // NOUT/4 threads
    float4 v = out[i];
    v.x *= v.x; v.y *= v.y; v.z *= v.z; v.w *= v.w;
    out[i] = v;
}

// ---------------------------------------------------------------------------
// Launch
//   Inputs (metadata order): 0 coordinates, 1 shifts, 2 rs, 3 inta,
//                            4 params, 5 numatoms, 6 atom_index, 7 species
// ---------------------------------------------------------------------------
extern "C" void kernel_launch(void* const* d_in, const int* in_sizes, int n_in,
                              void* d_out, int out_size) {
    const float* coords     = (const float*)d_in[0];
    const float* shifts     = (const float*)d_in[1];
    const float* rs         = (const float*)d_in[2];
    const float* inta       = (const float*)d_in[3];
    const int*   atom_index = (const int*)d_in[6];
    const int*   species    = (const int*)d_in[7];
    float*       out        = (float*)d_out;

    // zero accumulator: NOUT/4 float4 elements
    zero_kernel<<<(NOUT / 4) / 256, 256>>>((float4*)out);

    // one thread per pair
    pair_kernel<<<NPAIR / 256, 256>>>(coords, shifts, rs, inta,
                                      atom_index, species, out);

    // square in place
    square_kernel<<<(NOUT / 4) / 256, 256>>>((float4*)out);
}